// round 3
// baseline (speedup 1.0000x reference)
#include <cuda_runtime.h>

#define NB 8
#define NC 128
#define NA 16
#define NN 4096
#define BQ 64
#define BK 32
#define PSS 33   // padded P stride (bank-conflict-free broadcast reads)

// Scratch (allocation-free rule: __device__ globals)
__device__ float g_q[(size_t)NB * NA * NN];           // [B, A, N], prescaled by 1/sqrt(A)
__device__ float g_k[(size_t)NB * NA * NN];           // [B, A, N]
__device__ float g_v[(size_t)NB * NN * NC];           // [B, N, C]

// ---------------------------------------------------------------------------
// Projection: q = Wq x + bq (x0.25), k = Wk x + bk, v = Wv x + bv
// CTA = (n-tile of 64 pixels, batch). 256 threads.
// ---------------------------------------------------------------------------
__global__ __launch_bounds__(256) void proj_kernel(
    const float* __restrict__ x,
    const float* __restrict__ Wq, const float* __restrict__ bq,
    const float* __restrict__ Wk, const float* __restrict__ bk,
    const float* __restrict__ Wv, const float* __restrict__ bv)
{
    __shared__ float xs[NC * 64];     // xs[c][n], 32 KB
    const int b   = blockIdx.y;
    const int n0  = blockIdx.x * 64;
    const int tid = threadIdx.x;

    const float* xb = x + ((size_t)b * NC) * NN + n0;
    for (int idx = tid; idx < NC * 64; idx += 256) {
        int c = idx >> 6, n = idx & 63;
        xs[c * 64 + n] = xb[(size_t)c * NN + n];
    }
    __syncthreads();

    // 160 output rows x 64 pixels; within a warp o is constant, n consecutive
    for (int idx = tid; idx < 160 * 64; idx += 256) {
        int o = idx >> 6, n = idx & 63;
        const float* Wrow; float bias;
        if (o < 16)      { Wrow = Wq + o * NC;        bias = bq[o];      }
        else if (o < 32) { Wrow = Wk + (o - 16) * NC; bias = bk[o - 16]; }
        else             { Wrow = Wv + (o - 32) * NC; bias = bv[o - 32]; }

        float acc = bias;
        #pragma unroll
        for (int c = 0; c < NC; c += 4) {
            float4 w = *(const float4*)(Wrow + c);    // uniform across warp
            acc += w.x * xs[(c + 0) * 64 + n];
            acc += w.y * xs[(c + 1) * 64 + n];
            acc += w.z * xs[(c + 2) * 64 + n];
            acc += w.w * xs[(c + 3) * 64 + n];
        }
        int ng = n0 + n;
        if (o < 16)      g_q[((size_t)b * NA + o) * NN + ng] = acc * 0.25f; // prescale 1/sqrt(16)
        else if (o < 32) g_k[((size_t)b * NA + (o - 16)) * NN + ng] = acc;
        else             g_v[((size_t)b * NN + ng) * NC + (o - 32)] = acc;
    }
}

// ---------------------------------------------------------------------------
// Flash attention: CTA = (64-query tile, batch), 256 threads = 16(tx) x 16(ty).
// Thread owns O[4 rows][8 cols]. Online softmax, BK=32 keys per iteration.
// ---------------------------------------------------------------------------
__global__ __launch_bounds__(256) void attn_kernel(float* __restrict__ out)
{
    // One carved smem buffer: load phase needs 7744 floats, epilogue needs 8192.
    __shared__ float smem[NC * BQ];   // 8192 floats = 32 KB
    float* Qt = smem;                 // [16][64]  (1024)
    float* Kt = smem + 1024;          // [16][32]  (512)
    float* Vs = smem + 1536;          // [32][128] (4096)
    float* Ps = smem + 5632;          // [64][33]  (2112)

    const int b   = blockIdx.y;
    const int q0  = blockIdx.x * BQ;
    const int tid = threadIdx.x;
    const int tx  = tid & 15;
    const int ty  = tid >> 4;

    for (int idx = tid; idx < NA * BQ; idx += 256) {
        int a = idx >> 6, i = idx & 63;
        Qt[a * BQ + i] = g_q[((size_t)b * NA + a) * NN + q0 + i];  // already prescaled
    }

    float m[4], l[4], O[4][8];
    #pragma unroll
    for (int r = 0; r < 4; r++) {
        m[r] = -1e30f; l[r] = 0.f;
        #pragma unroll
        for (int c = 0; c < 8; c++) O[r][c] = 0.f;
    }
    __syncthreads();

    for (int kt = 0; kt < NN / BK; kt++) {
        const int k0 = kt * BK;
        // Load K tile [16][32] (transposed layout) and V tile [32][128]
        for (int idx = tid; idx < NA * BK; idx += 256) {
            int a = idx >> 5, j = idx & 31;
            Kt[a * BK + j] = g_k[((size_t)b * NA + a) * NN + k0 + j];
        }
        for (int idx = tid; idx < BK * NC / 4; idx += 256) {
            int j = idx >> 5, c4 = idx & 31;
            *(float4*)&Vs[j * NC + c4 * 4] =
                *(const float4*)&g_v[((size_t)b * NN + k0 + j) * NC + c4 * 4];
        }
        __syncthreads();

        // S = Q K^T   (thread tile 4 rows x 2 key-cols)
        float S[4][2];
        #pragma unroll
        for (int r = 0; r < 4; r++) { S[r][0] = 0.f; S[r][1] = 0.f; }
        #pragma unroll
        for (int a = 0; a < NA; a++) {
            float4 qv = *(float4*)&Qt[a * BQ + ty * 4];
            float2 kv = *(float2*)&Kt[a * BK + tx * 2];
            float qa[4] = {qv.x, qv.y, qv.z, qv.w};
            #pragma unroll
            for (int r = 0; r < 4; r++) {
                S[r][0] += qa[r] * kv.x;
                S[r][1] += qa[r] * kv.y;
            }
        }

        // Online softmax (row groups live in 16-lane shuffle groups)
        #pragma unroll
        for (int r = 0; r < 4; r++) {
            float rm = fmaxf(S[r][0], S[r][1]);
            #pragma unroll
            for (int w = 1; w < 16; w <<= 1)
                rm = fmaxf(rm, __shfl_xor_sync(0xffffffffu, rm, w));
            float mnew = fmaxf(m[r], rm);
            float corr = __expf(m[r] - mnew);
            m[r] = mnew;
            float p0 = __expf(S[r][0] - mnew);
            float p1 = __expf(S[r][1] - mnew);
            float rs = p0 + p1;
            #pragma unroll
            for (int w = 1; w < 16; w <<= 1)
                rs += __shfl_xor_sync(0xffffffffu, rs, w);
            l[r] = l[r] * corr + rs;
            #pragma unroll
            for (int c = 0; c < 8; c++) O[r][c] *= corr;
            Ps[(ty * 4 + r) * PSS + tx * 2 + 0] = p0;
            Ps[(ty * 4 + r) * PSS + tx * 2 + 1] = p1;
        }
        __syncthreads();

        // O += P V   (thread tile 4 x 8, float4 V loads)
        #pragma unroll 4
        for (int j = 0; j < BK; j++) {
            float4 va = *(float4*)&Vs[j * NC + tx * 8];
            float4 vb = *(float4*)&Vs[j * NC + tx * 8 + 4];
            #pragma unroll
            for (int r = 0; r < 4; r++) {
                float p = Ps[(ty * 4 + r) * PSS + j];
                O[r][0] += p * va.x; O[r][1] += p * va.y;
                O[r][2] += p * va.z; O[r][3] += p * va.w;
                O[r][4] += p * vb.x; O[r][5] += p * vb.y;
                O[r][6] += p * vb.z; O[r][7] += p * vb.w;
            }
        }
        __syncthreads();
    }

    // Epilogue: normalize, transpose through smem, coalesced store [B,C,N]
    float* Os = smem;   // [128][64]
    #pragma unroll
    for (int r = 0; r < 4; r++) {
        float inv = 1.0f / l[r];
        #pragma unroll
        for (int c = 0; c < 8; c++)
            Os[(tx * 8 + c) * BQ + ty * 4 + r] = O[r][c] * inv;
    }
    __syncthreads();

    float* outb = out + ((size_t)b * NC) * NN + q0;
    for (int idx = tid; idx < NC * BQ; idx += 256) {
        int c = idx >> 6, i = idx & 63;
        outb[(size_t)c * NN + i] = Os[c * BQ + i];
    }
}

// ---------------------------------------------------------------------------
extern "C" void kernel_launch(void* const* d_in, const int* in_sizes, int n_in,
                              void* d_out, int out_size)
{
    const float* x  = (const float*)d_in[0];
    const float* Wq = (const float*)d_in[1];
    const float* bq = (const float*)d_in[2];
    const float* Wk = (const float*)d_in[3];
    const float* bk = (const float*)d_in[4];
    const float* Wv = (const float*)d_in[5];
    const float* bv = (const float*)d_in[6];
    float* out = (float*)d_out;

    proj_kernel<<<dim3(NN / 64, NB), 256>>>(x, Wq, bq, Wk, bk, Wv, bv);
    attn_kernel<<<dim3(NN / BQ, NB), 256>>>(out);
}

// round 4
// speedup vs baseline: 2.1802x; 2.1802x over previous
#include <cuda_runtime.h>

#define NB 8
#define NC 128
#define NA 16
#define NN 4096
#define BQ 128
#define BK 32
#define PSTR 132   // P tile stride: [BK][BQ+4], 16B-aligned rows

typedef unsigned long long u64;

__device__ __forceinline__ u64 fma2(u64 a, u64 b, u64 c) {
    u64 d; asm("fma.rn.f32x2 %0,%1,%2,%3;" : "=l"(d) : "l"(a), "l"(b), "l"(c)); return d;
}
__device__ __forceinline__ u64 mul2(u64 a, u64 b) {
    u64 d; asm("mul.rn.f32x2 %0,%1,%2;" : "=l"(d) : "l"(a), "l"(b)); return d;
}
__device__ __forceinline__ u64 pack2(float lo, float hi) {
    u64 d; asm("mov.b64 %0,{%1,%2};" : "=l"(d) : "f"(lo), "f"(hi)); return d;
}
__device__ __forceinline__ float2 unpack2(u64 d) {
    float2 r; asm("mov.b64 {%0,%1},%2;" : "=f"(r.x), "=f"(r.y) : "l"(d)); return r;
}

// Scratch (allocation-free rule: __device__ globals)
__device__ float g_q[(size_t)NB * NA * NN];   // [B, A, N], prescaled by 1/sqrt(A)
__device__ float g_k[(size_t)NB * NA * NN];   // [B, A, N]
__device__ float g_v[(size_t)NB * NN * NC];   // [B, N, C]

// ---------------------------------------------------------------------------
// Projection: q = Wq x + bq (x0.25), k = Wk x + bk, v = Wv x + bv
// ---------------------------------------------------------------------------
__global__ __launch_bounds__(256) void proj_kernel(
    const float* __restrict__ x,
    const float* __restrict__ Wq, const float* __restrict__ bq,
    const float* __restrict__ Wk, const float* __restrict__ bk,
    const float* __restrict__ Wv, const float* __restrict__ bv)
{
    __shared__ float xs[NC * 64];
    const int b   = blockIdx.y;
    const int n0  = blockIdx.x * 64;
    const int tid = threadIdx.x;

    const float* xb = x + ((size_t)b * NC) * NN + n0;
    for (int idx = tid; idx < NC * 64; idx += 256) {
        int c = idx >> 6, n = idx & 63;
        xs[c * 64 + n] = xb[(size_t)c * NN + n];
    }
    __syncthreads();

    for (int idx = tid; idx < 160 * 64; idx += 256) {
        int o = idx >> 6, n = idx & 63;
        const float* Wrow; float bias;
        if (o < 16)      { Wrow = Wq + o * NC;        bias = bq[o];      }
        else if (o < 32) { Wrow = Wk + (o - 16) * NC; bias = bk[o - 16]; }
        else             { Wrow = Wv + (o - 32) * NC; bias = bv[o - 32]; }

        float acc = bias;
        #pragma unroll
        for (int c = 0; c < NC; c += 4) {
            float4 w = *(const float4*)(Wrow + c);
            acc += w.x * xs[(c + 0) * 64 + n];
            acc += w.y * xs[(c + 1) * 64 + n];
            acc += w.z * xs[(c + 2) * 64 + n];
            acc += w.w * xs[(c + 3) * 64 + n];
        }
        int ng = n0 + n;
        if (o < 16)      g_q[((size_t)b * NA + o) * NN + ng] = acc * 0.25f;
        else if (o < 32) g_k[((size_t)b * NA + (o - 16)) * NN + ng] = acc;
        else             g_v[((size_t)b * NN + ng) * NC + (o - 32)] = acc;
    }
}

// ---------------------------------------------------------------------------
// Flash attention, FFMA2 version.
// CTA = (128-query tile, batch), 256 threads = 16(tx) x 16(ty).
// Thread tile: 8 query rows (ty*8..+7) x 8 V-channels (tx*8..+7), packed pairs.
// S tile: 8 rows x 2 key-cols (tx*2, tx*2+1), packed over row-pairs.
// ---------------------------------------------------------------------------
__global__ __launch_bounds__(256, 2) void attn_kernel(float* __restrict__ out)
{
    // Union layout (floats): Qt[16][128]=2048 | Kt[16][32]=512 | Vs[32][128]=4096
    //                        | Ps[32][132]=4224  -> total 10880 floats = 42.5 KB
    // Epilogue reuses the front 8192 floats as Os[128][64].
    __shared__ __align__(16) float smem[10880];
    float* Qt = smem;           // [16][BQ]
    float* Kt = smem + 2048;    // [16][BK]
    float* Vs = smem + 2560;    // [BK][NC]
    float* Ps = smem + 6656;    // [BK][PSTR]  (transposed: [key][query])

    const int b   = blockIdx.y;
    const int q0  = blockIdx.x * BQ;
    const int tid = threadIdx.x;
    const int tx  = tid & 15;
    const int ty  = tid >> 4;

    // Load Q tile [16][128] (prescaled)
    for (int idx = tid; idx < NA * BQ; idx += 256) {
        int a = idx >> 7, i = idx & 127;
        Qt[a * BQ + i] = g_q[((size_t)b * NA + a) * NN + q0 + i];
    }

    float m[8], l[8];
    u64 O2[8][4];   // [row][col-pair]: cols (tx*8+2c, tx*8+2c+1)
    #pragma unroll
    for (int r = 0; r < 8; r++) {
        m[r] = -1e30f; l[r] = 0.f;
        #pragma unroll
        for (int c = 0; c < 4; c++) O2[r][c] = 0ull;
    }
    __syncthreads();

    for (int kt = 0; kt < NN / BK; kt++) {
        const int k0 = kt * BK;
        // Load K tile [16][32] and V tile [32][128]
        for (int idx = tid; idx < NA * BK; idx += 256) {
            int a = idx >> 5, j = idx & 31;
            Kt[a * BK + j] = g_k[((size_t)b * NA + a) * NN + k0 + j];
        }
        for (int idx = tid; idx < BK * NC / 4; idx += 256) {
            int j = idx >> 5, c4 = idx & 31;
            *(float4*)&Vs[j * NC + c4 * 4] =
                *(const float4*)&g_v[((size_t)b * NN + k0 + j) * NC + c4 * 4];
        }
        __syncthreads();

        // S = Q K^T, packed over row-pairs: S2[rp][c] = (S[2rp][c], S[2rp+1][c])
        u64 S2[4][2];
        #pragma unroll
        for (int rp = 0; rp < 4; rp++) { S2[rp][0] = 0ull; S2[rp][1] = 0ull; }
        #pragma unroll
        for (int a = 0; a < NA; a++) {
            ulonglong2 q01 = *(const ulonglong2*)&Qt[a * BQ + ty * 8];
            ulonglong2 q23 = *(const ulonglong2*)&Qt[a * BQ + ty * 8 + 4];
            float2 kv = *(const float2*)&Kt[a * BK + tx * 2];
            u64 kk0 = pack2(kv.x, kv.x);
            u64 kk1 = pack2(kv.y, kv.y);
            S2[0][0] = fma2(q01.x, kk0, S2[0][0]); S2[0][1] = fma2(q01.x, kk1, S2[0][1]);
            S2[1][0] = fma2(q01.y, kk0, S2[1][0]); S2[1][1] = fma2(q01.y, kk1, S2[1][1]);
            S2[2][0] = fma2(q23.x, kk0, S2[2][0]); S2[2][1] = fma2(q23.x, kk1, S2[2][1]);
            S2[3][0] = fma2(q23.y, kk0, S2[3][0]); S2[3][1] = fma2(q23.y, kk1, S2[3][1]);
        }

        // Unpack S, online softmax per row (16-lane shuffle groups over tx)
        float S[8][2];
        #pragma unroll
        for (int rp = 0; rp < 4; rp++) {
            float2 u0 = unpack2(S2[rp][0]);
            float2 u1 = unpack2(S2[rp][1]);
            S[2 * rp][0] = u0.x; S[2 * rp + 1][0] = u0.y;
            S[2 * rp][1] = u1.x; S[2 * rp + 1][1] = u1.y;
        }
        #pragma unroll
        for (int r = 0; r < 8; r++) {
            float rm = fmaxf(S[r][0], S[r][1]);
            #pragma unroll
            for (int w = 1; w < 16; w <<= 1)
                rm = fmaxf(rm, __shfl_xor_sync(0xffffffffu, rm, w));
            float mnew = fmaxf(m[r], rm);
            float corr = __expf(m[r] - mnew);
            m[r] = mnew;
            float p0 = __expf(S[r][0] - mnew);
            float p1 = __expf(S[r][1] - mnew);
            float rs = p0 + p1;
            #pragma unroll
            for (int w = 1; w < 16; w <<= 1)
                rs += __shfl_xor_sync(0xffffffffu, rs, w);
            l[r] = l[r] * corr + rs;
            u64 cp = pack2(corr, corr);
            #pragma unroll
            for (int c = 0; c < 4; c++) O2[r][c] = mul2(cp, O2[r][c]);
            Ps[(tx * 2 + 0) * PSTR + ty * 8 + r] = p0;
            Ps[(tx * 2 + 1) * PSTR + ty * 8 + r] = p1;
        }
        __syncthreads();

        // O += P V  (per j: 2 LDS.128 V + 2 LDS.128 P, 32 FFMA2)
        #pragma unroll 2
        for (int j = 0; j < BK; j++) {
            const float* vrow = &Vs[j * NC + tx * 8];
            ulonglong2 va = *(const ulonglong2*)vrow;
            ulonglong2 vb = *(const ulonglong2*)(vrow + 4);
            float4 pa = *(const float4*)&Ps[j * PSTR + ty * 8];
            float4 pb = *(const float4*)&Ps[j * PSTR + ty * 8 + 4];
            float pr[8] = {pa.x, pa.y, pa.z, pa.w, pb.x, pb.y, pb.z, pb.w};
            #pragma unroll
            for (int r = 0; r < 8; r++) {
                u64 pp = pack2(pr[r], pr[r]);
                O2[r][0] = fma2(pp, va.x, O2[r][0]);
                O2[r][1] = fma2(pp, va.y, O2[r][1]);
                O2[r][2] = fma2(pp, vb.x, O2[r][2]);
                O2[r][3] = fma2(pp, vb.y, O2[r][3]);
            }
        }
        __syncthreads();
    }

    // Epilogue: normalize, transpose through smem in 2 half-passes, coalesced store
    float inv[8];
    #pragma unroll
    for (int r = 0; r < 8; r++) inv[r] = 1.0f / l[r];

    float* Os = smem;   // [128 channels][64 queries] = 32 KB
    float* outb = out + ((size_t)b * NC) * NN + q0;
    #pragma unroll
    for (int half = 0; half < 2; half++) {
        __syncthreads();
        if ((ty >> 3) == half) {
            int tyl = ty & 7;
            #pragma unroll
            for (int r = 0; r < 8; r++) {
                #pragma unroll
                for (int c = 0; c < 4; c++) {
                    float2 o = unpack2(O2[r][c]);
                    Os[(tx * 8 + 2 * c) * 64 + tyl * 8 + r]     = o.x * inv[r];
                    Os[(tx * 8 + 2 * c + 1) * 64 + tyl * 8 + r] = o.y * inv[r];
                }
            }
        }
        __syncthreads();
        for (int idx = tid; idx < NC * 64; idx += 256) {
            int c = idx >> 6, i = idx & 63;
            outb[(size_t)c * NN + half * 64 + i] = Os[c * 64 + i];
        }
    }
}

// ---------------------------------------------------------------------------
extern "C" void kernel_launch(void* const* d_in, const int* in_sizes, int n_in,
                              void* d_out, int out_size)
{
    const float* x  = (const float*)d_in[0];
    const float* Wq = (const float*)d_in[1];
    const float* bq = (const float*)d_in[2];
    const float* Wk = (const float*)d_in[3];
    const float* bk = (const float*)d_in[4];
    const float* Wv = (const float*)d_in[5];
    const float* bv = (const float*)d_in[6];
    float* out = (float*)d_out;

    proj_kernel<<<dim3(NN / 64, NB), 256>>>(x, Wq, bq, Wk, bk, Wv, bv);
    attn_kernel<<<dim3(NN / BQ, NB), 256>>>(out);
}

// round 9
// speedup vs baseline: 7.3110x; 3.3533x over previous
#include <cuda_runtime.h>
#include <cstdint>

#define NB 8
#define NC 128
#define NA 16
#define NN 4096
#define BQ 128
#define BKV 64
#define NKT (NN / BKV)   // 64

// ---------------------------------------------------------------------------
// Portable PTX helpers (no sm_103a-specific instructions!)
// ---------------------------------------------------------------------------
__device__ __forceinline__ uint32_t smem_u32(const void* p) {
    uint32_t a;
    asm("{ .reg .u64 t; cvta.to.shared.u64 t, %1; cvt.u32.u64 %0, t; }" : "=r"(a) : "l"(p));
    return a;
}
__device__ __forceinline__ float tf32r(float x) {   // round-to-nearest tf32
    float y; asm("cvt.rna.tf32.f32 %0,%1;" : "=f"(y) : "f"(x)); return y;
}
__device__ __forceinline__ void cp16(uint32_t dst, const void* src) {
    asm volatile("cp.async.cg.shared.global [%0], [%1], 16;" :: "r"(dst), "l"(src));
}
#define CP_COMMIT() asm volatile("cp.async.commit_group;" ::: "memory")
#define CP_WAIT(n)  asm volatile("cp.async.wait_group %0;" :: "n"(n) : "memory")

// m16n8k8 tf32 mma: D(f32) += A(tf32) * B(tf32)
__device__ __forceinline__ void mma8(float* d, uint32_t a0, uint32_t a1, uint32_t a2, uint32_t a3,
                                     float bx, float by) {
    asm volatile(
        "mma.sync.aligned.m16n8k8.row.col.f32.tf32.tf32.f32 "
        "{%0,%1,%2,%3}, {%4,%5,%6,%7}, {%8,%9}, {%0,%1,%2,%3};"
        : "+f"(d[0]), "+f"(d[1]), "+f"(d[2]), "+f"(d[3])
        : "r"(a0), "r"(a1), "r"(a2), "r"(a3),
          "r"(__float_as_uint(bx)), "r"(__float_as_uint(by)));
}

// ---------------------------------------------------------------------------
// Pre-packed operand images (written by proj_kernel, fragment-ordered):
//  g_qp[b][qg=0..255][ks=0..3][lane][4]  : A-frags (a0,a1,a2,a3), q split hi/lo
//  g_kp[b][kb=0..511][ks2=0..1][lane][4] : B-frags (b0,b1)@ks=2ks2, (b0,b1)@2ks2+1
//  g_vp[b][kg=0..511][c4=0..7][lane][4]  : B-frags (b0,b1)@nb2=2c4, (b0,b1)@2c4+1
// ---------------------------------------------------------------------------
__device__ float g_qp[(size_t)NB * 256 * 4 * 32 * 4];    // 4 MB
__device__ float g_kp[(size_t)NB * 512 * 2 * 32 * 4];    // 4 MB
__device__ float g_vp[(size_t)NB * 512 * 8 * 32 * 4];    // 16 MB

// ---------------------------------------------------------------------------
// Projection + fragment packing
// ---------------------------------------------------------------------------
__global__ __launch_bounds__(256) void proj_kernel(
    const float* __restrict__ x,
    const float* __restrict__ Wq, const float* __restrict__ bq,
    const float* __restrict__ Wk, const float* __restrict__ bk,
    const float* __restrict__ Wv, const float* __restrict__ bv)
{
    __shared__ float xs[NC * 64];
    const int b   = blockIdx.y;
    const int n0  = blockIdx.x * 64;
    const int tid = threadIdx.x;

    const float* xb = x + ((size_t)b * NC) * NN + n0;
    for (int idx = tid; idx < NC * 64; idx += 256) {
        int c = idx >> 6, n = idx & 63;
        xs[c * 64 + n] = xb[(size_t)c * NN + n];
    }
    __syncthreads();

    for (int idx = tid; idx < 160 * 64; idx += 256) {
        int o = idx >> 6, n = idx & 63;
        const float* Wrow; float bias;
        if (o < 16)      { Wrow = Wq + o * NC;        bias = bq[o];      }
        else if (o < 32) { Wrow = Wk + (o - 16) * NC; bias = bk[o - 16]; }
        else             { Wrow = Wv + (o - 32) * NC; bias = bv[o - 32]; }

        float acc = bias;
        #pragma unroll
        for (int c = 0; c < NC; c += 4) {
            float4 w = *(const float4*)(Wrow + c);
            acc += w.x * xs[(c + 0) * 64 + n];
            acc += w.y * xs[(c + 1) * 64 + n];
            acc += w.z * xs[(c + 2) * 64 + n];
            acc += w.w * xs[(c + 3) * 64 + n];
        }
        const int ng = n0 + n;

        if (o < 16) {
            // Q: prescale by 1/sqrt(A)=0.25, split hi/lo across channels o and o+16
            float q  = acc * 0.25f;
            float qh = tf32r(q);
            float ql = tf32r(q - qh);
            int qg = ng >> 4, g16 = ng & 15;
            size_t base = ((size_t)b * 256 + qg) * 4;
            #pragma unroll
            for (int s = 0; s < 2; s++) {
                int ch = o + 16 * s;
                int ks = ch >> 3, t2 = ch & 7;
                int lane = ((g16 & 7) << 2) | (t2 & 3);
                int j = (g16 >> 3) | ((t2 >> 2) << 1);
                g_qp[((base + ks) * 32 + lane) * 4 + j] = s ? ql : qh;
            }
        } else if (o < 32) {
            // K: rounded hi, duplicated into channels a and a+16
            float kh = tf32r(acc);
            int a = o - 16;
            int kb = ng >> 3, gk = ng & 7;
            size_t base = ((size_t)b * 512 + kb) * 2;
            #pragma unroll
            for (int s = 0; s < 2; s++) {
                int ch = a + 16 * s;
                int ks = ch >> 3, t2 = ch & 7, ks2 = ks >> 1;
                int lane = (gk << 2) | (t2 & 3);
                int j = ((ks & 1) << 1) | (t2 >> 2);
                g_kp[((base + ks2) * 32 + lane) * 4 + j] = kh;
            }
        } else {
            float vv = tf32r(acc);
            int c = o - 32;
            int kg = ng >> 3, r = ng & 7;
            int lane = ((c & 7) << 2) | (r & 3);
            int c4 = c >> 4, w2 = (c >> 3) & 1;
            int j = (w2 << 1) | (r >> 2);
            g_vp[((((size_t)b * 512 + kg) * 8 + c4) * 32 + lane) * 4 + j] = vv;
        }
    }
}

// ---------------------------------------------------------------------------
// tf32 mma.sync flash attention. CTA = 128 queries x batch, 8 warps.
// Warp w owns rows q0 + 16w .. +15; S/P register-resident; no-max softmax.
// ---------------------------------------------------------------------------
// dynamic smem: Qs [8][4][32]f4 @0 (16KB) | Ks 2x[8][2][32]f4 @16K (16KB)
//               Vs 2x[8][8][32]f4 @32K (64KB)   total 96 KB
#define SMEM_TOTAL 98304

__global__ __launch_bounds__(256, 2) void attn_kernel(float* __restrict__ out)
{
    extern __shared__ __align__(16) char smc[];
    const float4* Qs = (const float4*)smc;
    const float4* Ks = (const float4*)(smc + 16384);
    const float4* Vs = (const float4*)(smc + 32768);
    const uint32_t sb = smem_u32(smc);

    const int b    = blockIdx.y;
    const int qx   = blockIdx.x;
    const int tid  = threadIdx.x;
    const int w    = tid >> 5;
    const int lane = tid & 31;

    // cp.async sources (fragment-packed, contiguous per tile)
    const char* qsrc = (const char*)g_qp + ((size_t)b * 256 + qx * 8) * 2048;   // 16KB
    const char* kbase = (const char*)g_kp + (size_t)b * 512 * 1024;             // 1KB per kb
    const char* vbase = (const char*)g_vp + (size_t)b * 512 * 4096;             // 4KB per kg

    // prologue: Q + tile 0
    #pragma unroll
    for (int i = 0; i < 4; i++) {
        int ch = tid + 256 * i;
        cp16(sb + ch * 16, qsrc + ch * 16);
    }
    {
        const char* ks = kbase;         // kt=0
        const char* vs = vbase;
        #pragma unroll
        for (int i = 0; i < 2; i++) { int ch = tid + 256 * i; cp16(sb + 16384 + ch * 16, ks + ch * 16); }
        #pragma unroll
        for (int i = 0; i < 8; i++) { int ch = tid + 256 * i; cp16(sb + 32768 + ch * 16, vs + ch * 16); }
    }
    CP_COMMIT();

    float O[16][4];
    #pragma unroll
    for (int n2 = 0; n2 < 16; n2++) { O[n2][0] = O[n2][1] = O[n2][2] = O[n2][3] = 0.f; }
    float lsum_lo = 0.f, lsum_hi = 0.f;

    const int t4   = lane & 3;
    const int src1 = (lane & ~3) | (t4 >> 1);
    const int src2 = src1 + 2;
    const bool odd = t4 & 1;

    for (int kt = 0; kt < NKT; kt++) {
        const int buf = kt & 1;
        if (kt < NKT - 1) {
            const int nb = (kt + 1) & 1;
            const char* ks = kbase + (size_t)(kt + 1) * 8192;
            const char* vs = vbase + (size_t)(kt + 1) * 32768;
            #pragma unroll
            for (int i = 0; i < 2; i++) { int ch = tid + 256 * i; cp16(sb + 16384 + nb * 8192 + ch * 16, ks + ch * 16); }
            #pragma unroll
            for (int i = 0; i < 8; i++) { int ch = tid + 256 * i; cp16(sb + 32768 + nb * 32768 + ch * 16, vs + ch * 16); }
            CP_COMMIT();
            CP_WAIT(1);
        } else {
            CP_WAIT(0);
        }
        __syncthreads();

        // ---- QK: S[16 rows][64 keys] per warp ----
        float S[8][4];
        #pragma unroll
        for (int nb = 0; nb < 8; nb++) { S[nb][0] = S[nb][1] = S[nb][2] = S[nb][3] = 0.f; }

        float4 A0 = Qs[(w * 4 + 0) * 32 + lane];
        float4 A1 = Qs[(w * 4 + 1) * 32 + lane];
        float4 A2 = Qs[(w * 4 + 2) * 32 + lane];
        float4 A3 = Qs[(w * 4 + 3) * 32 + lane];

        #pragma unroll
        for (int nb = 0; nb < 8; nb++) {
            float4 K0 = Ks[buf * 512 + (nb * 2 + 0) * 32 + lane];
            float4 K1 = Ks[buf * 512 + (nb * 2 + 1) * 32 + lane];
            mma8(S[nb], __float_as_uint(A0.x), __float_as_uint(A0.y), __float_as_uint(A0.z), __float_as_uint(A0.w), K0.x, K0.y);
            mma8(S[nb], __float_as_uint(A1.x), __float_as_uint(A1.y), __float_as_uint(A1.z), __float_as_uint(A1.w), K0.z, K0.w);
            mma8(S[nb], __float_as_uint(A2.x), __float_as_uint(A2.y), __float_as_uint(A2.z), __float_as_uint(A2.w), K1.x, K1.y);
            mma8(S[nb], __float_as_uint(A3.x), __float_as_uint(A3.y), __float_as_uint(A3.z), __float_as_uint(A3.w), K1.z, K1.w);
        }

        // ---- exp + row sums (quad reduce) ----
        float rlo = 0.f, rhi = 0.f;
        #pragma unroll
        for (int nb = 0; nb < 8; nb++) {
            S[nb][0] = __expf(S[nb][0]);
            S[nb][1] = __expf(S[nb][1]);
            S[nb][2] = __expf(S[nb][2]);
            S[nb][3] = __expf(S[nb][3]);
            rlo += S[nb][0] + S[nb][1];
            rhi += S[nb][2] + S[nb][3];
        }
        rlo += __shfl_xor_sync(0xffffffffu, rlo, 1);
        rlo += __shfl_xor_sync(0xffffffffu, rlo, 2);
        rhi += __shfl_xor_sync(0xffffffffu, rhi, 1);
        rhi += __shfl_xor_sync(0xffffffffu, rhi, 2);
        lsum_lo += rlo;
        lsum_hi += rhi;

        // ---- PV: O[16 rows][128 ch] += P[16][64] * V[64][128] ----
        #pragma unroll
        for (int ksv = 0; ksv < 8; ksv++) {
            // C-frag (cols 8ksv..8ksv+7) -> A-frag remap within quad
            float s0 = __shfl_sync(0xffffffffu, S[ksv][0], src1);
            float s1 = __shfl_sync(0xffffffffu, S[ksv][1], src1);
            float s2 = __shfl_sync(0xffffffffu, S[ksv][2], src1);
            float s3 = __shfl_sync(0xffffffffu, S[ksv][3], src1);
            float u0 = __shfl_sync(0xffffffffu, S[ksv][0], src2);
            float u1 = __shfl_sync(0xffffffffu, S[ksv][1], src2);
            float u2 = __shfl_sync(0xffffffffu, S[ksv][2], src2);
            float u3 = __shfl_sync(0xffffffffu, S[ksv][3], src2);
            uint32_t a0 = __float_as_uint(tf32r(odd ? s1 : s0));
            uint32_t a1 = __float_as_uint(tf32r(odd ? s3 : s2));
            uint32_t a2 = __float_as_uint(tf32r(odd ? u1 : u0));
            uint32_t a3 = __float_as_uint(tf32r(odd ? u3 : u2));
            #pragma unroll
            for (int c4 = 0; c4 < 8; c4++) {
                float4 Vf = Vs[buf * 2048 + (ksv * 8 + c4) * 32 + lane];
                mma8(O[2 * c4],     a0, a1, a2, a3, Vf.x, Vf.y);
                mma8(O[2 * c4 + 1], a0, a1, a2, a3, Vf.z, Vf.w);
            }
        }
        __syncthreads();
    }

    // ---- epilogue: normalize + store (out[b][ch][n]) ----
    const float inv_lo = 1.0f / lsum_lo;
    const float inv_hi = 1.0f / lsum_hi;
    const int q_lo = qx * BQ + w * 16 + (lane >> 2);
    const int q_hi = q_lo + 8;
    float* ob = out + (size_t)b * NC * NN;
    #pragma unroll
    for (int n2 = 0; n2 < 16; n2++) {
        int ch = n2 * 8 + 2 * (lane & 3);
        ob[(size_t)ch * NN + q_lo]       = O[n2][0] * inv_lo;
        ob[(size_t)(ch + 1) * NN + q_lo] = O[n2][1] * inv_lo;
        ob[(size_t)ch * NN + q_hi]       = O[n2][2] * inv_hi;
        ob[(size_t)(ch + 1) * NN + q_hi] = O[n2][3] * inv_hi;
    }
}

// ---------------------------------------------------------------------------
extern "C" void kernel_launch(void* const* d_in, const int* in_sizes, int n_in,
                              void* d_out, int out_size)
{
    const float* x  = (const float*)d_in[0];
    const float* Wq = (const float*)d_in[1];
    const float* bq = (const float*)d_in[2];
    const float* Wk = (const float*)d_in[3];
    const float* bk = (const float*)d_in[4];
    const float* Wv = (const float*)d_in[5];
    const float* bv = (const float*)d_in[6];
    float* out = (float*)d_out;

    (void)cudaFuncSetAttribute(attn_kernel, cudaFuncAttributeMaxDynamicSharedMemorySize, SMEM_TOTAL);

    proj_kernel<<<dim3(NN / 64, NB), 256>>>(x, Wq, bq, Wk, bk, Wv, bv);
    attn_kernel<<<dim3(NN / BQ, NB), 256, SMEM_TOTAL>>>(out);
}

// round 11
// speedup vs baseline: 9.2834x; 1.2698x over previous
#include <cuda_runtime.h>
#include <cstdint>

#define NB 8
#define NC 128
#define NA 16
#define NN 4096
#define BQ 128
#define BKV 64
#define NKT (NN / BKV)   // 64

// ---------------------------------------------------------------------------
// Portable PTX helpers
// ---------------------------------------------------------------------------
__device__ __forceinline__ uint32_t smem_u32(const void* p) {
    uint32_t a;
    asm("{ .reg .u64 t; cvta.to.shared.u64 t, %1; cvt.u32.u64 %0, t; }" : "=r"(a) : "l"(p));
    return a;
}
__device__ __forceinline__ float tf32r(float x) {   // round-to-nearest tf32
    float y; asm("cvt.rna.tf32.f32 %0,%1;" : "=f"(y) : "f"(x)); return y;
}
__device__ __forceinline__ void cp16(uint32_t dst, const void* src) {
    asm volatile("cp.async.cg.shared.global [%0], [%1], 16;" :: "r"(dst), "l"(src));
}
#define CP_COMMIT() asm volatile("cp.async.commit_group;" ::: "memory")
#define CP_WAIT(n)  asm volatile("cp.async.wait_group %0;" :: "n"(n) : "memory")

// m16n8k8 tf32 mma: D(f32) += A(tf32) * B(tf32)
__device__ __forceinline__ void mma8(float* d, uint32_t a0, uint32_t a1, uint32_t a2, uint32_t a3,
                                     float bx, float by) {
    asm volatile(
        "mma.sync.aligned.m16n8k8.row.col.f32.tf32.tf32.f32 "
        "{%0,%1,%2,%3}, {%4,%5,%6,%7}, {%8,%9}, {%0,%1,%2,%3};"
        : "+f"(d[0]), "+f"(d[1]), "+f"(d[2]), "+f"(d[3])
        : "r"(a0), "r"(a1), "r"(a2), "r"(a3),
          "r"(__float_as_uint(bx)), "r"(__float_as_uint(by)));
}

// ---------------------------------------------------------------------------
// Pre-packed operand images (fragment-ordered):
//  g_qp[b][qg=0..255][ks=0..1][lane][4] : Q A-frags (single rna tf32, prescaled)
//  g_kp[b][kb=0..511][lane][4]          : K B-frags (b0,b1)@ks0 , (b0,b1)@ks1
//  g_vp[b][kg=0..511][c4=0..7][lane][4] : V B-frags (b0,b1)@nb2=2c4, (b0,b1)@2c4+1
// ---------------------------------------------------------------------------
__device__ float g_qp[(size_t)NB * 256 * 2 * 32 * 4];    // 2 MB
__device__ float g_kp[(size_t)NB * 512 * 32 * 4];        // 2 MB
__device__ float g_vp[(size_t)NB * 512 * 8 * 32 * 4];    // 16 MB

// ---------------------------------------------------------------------------
// Projection v2: register-tiled GEMM (out[160][128] per CTA of 128 pixels).
// Thread (tx,ty) owns 10 o-rows x 8 pixels. ~0.15 LDS/FMA.
// dynamic smem: xs[128][128] @0 (64KB) | Ws[160][17] @65536 (10.9KB)
// ---------------------------------------------------------------------------
#define WS_STR 17
#define PROJ_SMEM (65536 + 160 * WS_STR * 4)   // 76416 B

__global__ __launch_bounds__(256, 2) void proj_kernel(
    const float* __restrict__ x,
    const float* __restrict__ Wq, const float* __restrict__ bq,
    const float* __restrict__ Wk, const float* __restrict__ bk,
    const float* __restrict__ Wv, const float* __restrict__ bv)
{
    extern __shared__ __align__(16) float ps[];
    float* xs = ps;            // [128 c][128 n]
    float* Ws = ps + 16384;    // [160 o][WS_STR]

    const int b   = blockIdx.y;
    const int n0  = blockIdx.x * 128;
    const int tid = threadIdx.x;
    const int tx  = tid & 15;     // pixel group: n = tx*8..+7
    const int ty  = tid >> 4;     // o group: o = ty*10..+9

    const float* xb = x + ((size_t)b * NC) * NN + n0;
    for (int idx = tid; idx < 128 * 128; idx += 256) {
        int c = idx >> 7, n = idx & 127;
        xs[c * 128 + n] = xb[(size_t)c * NN + n];
    }

    float acc[10][8];
    #pragma unroll
    for (int oo = 0; oo < 10; oo++)
        #pragma unroll
        for (int i = 0; i < 8; i++) acc[oo][i] = 0.f;

    for (int chunk = 0; chunk < 8; chunk++) {
        __syncthreads();   // xs ready (first iter) / previous chunk consumed
        for (int idx = tid; idx < 160 * 16; idx += 256) {
            int o = idx >> 4, cc = idx & 15, c = chunk * 16 + cc;
            float wv;
            if (o < 16)      wv = Wq[o * NC + c];
            else if (o < 32) wv = Wk[(o - 16) * NC + c];
            else             wv = Wv[(o - 32) * NC + c];
            Ws[o * WS_STR + cc] = wv;
        }
        __syncthreads();

        #pragma unroll
        for (int cc = 0; cc < 16; cc++) {
            const int c = chunk * 16 + cc;
            float4 xa = *(const float4*)&xs[c * 128 + tx * 8];
            float4 xb2 = *(const float4*)&xs[c * 128 + tx * 8 + 4];
            float xv[8] = {xa.x, xa.y, xa.z, xa.w, xb2.x, xb2.y, xb2.z, xb2.w};
            #pragma unroll
            for (int oo = 0; oo < 10; oo++) {
                float wv = Ws[(ty * 10 + oo) * WS_STR + cc];
                #pragma unroll
                for (int i = 0; i < 8; i++) acc[oo][i] += wv * xv[i];
            }
        }
    }

    // epilogue: bias + tf32 round + fragment-pack stores
    #pragma unroll
    for (int oo = 0; oo < 10; oo++) {
        const int o = ty * 10 + oo;
        #pragma unroll
        for (int i = 0; i < 8; i++) {
            const int ng = n0 + tx * 8 + i;
            if (o < 16) {
                float q = (acc[oo][i] + bq[o]) * 0.25f;
                float qh = tf32r(q);
                int qg = ng >> 4, g16 = ng & 15;
                int ks = o >> 3, t2 = o & 7;
                int lane = ((g16 & 7) << 2) | (t2 & 3);
                int j = (g16 >> 3) | ((t2 >> 2) << 1);
                g_qp[(((size_t)b * 256 + qg) * 2 + ks) * 128 + lane * 4 + j] = qh;
            } else if (o < 32) {
                int a = o - 16;
                float kh = tf32r(acc[oo][i] + bk[a]);
                int kb = ng >> 3, gk = ng & 7;
                int ks = a >> 3, t2 = a & 7;
                int lane = (gk << 2) | (t2 & 3);
                int j = (ks << 1) | (t2 >> 2);
                g_kp[(((size_t)b * 512 + kb) * 32 + lane) * 4 + j] = kh;
            } else {
                int c = o - 32;
                float vv = tf32r(acc[oo][i] + bv[c]);
                int kg = ng >> 3, r = ng & 7;
                int lane = ((c & 7) << 2) | (r & 3);
                int c4 = c >> 4, w2 = (c >> 3) & 1;
                int j = (w2 << 1) | (r >> 2);
                g_vp[((((size_t)b * 512 + kg) * 8 + c4) * 32 + lane) * 4 + j] = vv;
            }
        }
    }
}

// ---------------------------------------------------------------------------
// tf32 mma.sync flash attention. CTA = 128 queries x batch, 8 warps.
// Warp w owns 16 rows; S/P register-resident; no-max softmax; Q frags hoisted.
// dynamic smem: Qs [8][2][32]f4 @0 (8KB) | Ks 2x[8][32]f4 @8192 (8KB)
//               Vs 2x[8][8][32]f4 @16384 (64KB)   total 80KB
// ---------------------------------------------------------------------------
#define SMEM_TOTAL 81920

__global__ __launch_bounds__(256, 2) void attn_kernel(float* __restrict__ out)
{
    extern __shared__ __align__(16) char smc[];
    const float4* Qs = (const float4*)smc;
    const float4* Ks = (const float4*)(smc + 8192);
    const float4* Vs = (const float4*)(smc + 16384);
    const uint32_t sb = smem_u32(smc);

    const int b    = blockIdx.y;
    const int qx   = blockIdx.x;
    const int tid  = threadIdx.x;
    const int w    = tid >> 5;
    const int lane = tid & 31;

    const char* qsrc  = (const char*)g_qp + ((size_t)b * 256 + qx * 8) * 1024;  // 8KB
    const char* kbase = (const char*)g_kp + (size_t)b * 512 * 512;              // 512B per kb
    const char* vbase = (const char*)g_vp + (size_t)b * 512 * 4096;             // 4KB per kg

    // prologue: Q + tile 0, then drain so Q frags can be hoisted into regs
    #pragma unroll
    for (int i = 0; i < 2; i++) { int ch = tid + 256 * i; cp16(sb + ch * 16, qsrc + ch * 16); }
    cp16(sb + 8192 + tid * 16, kbase + tid * 16);
    #pragma unroll
    for (int i = 0; i < 8; i++) { int ch = tid + 256 * i; cp16(sb + 16384 + ch * 16, vbase + ch * 16); }
    CP_COMMIT();
    CP_WAIT(0);
    __syncthreads();

    const float4 A0 = Qs[(w * 2 + 0) * 32 + lane];   // loop-invariant Q A-frags
    const float4 A1 = Qs[(w * 2 + 1) * 32 + lane];
    const uint32_t a00 = __float_as_uint(A0.x), a01 = __float_as_uint(A0.y),
                   a02 = __float_as_uint(A0.z), a03 = __float_as_uint(A0.w);
    const uint32_t a10 = __float_as_uint(A1.x), a11 = __float_as_uint(A1.y),
                   a12 = __float_as_uint(A1.z), a13 = __float_as_uint(A1.w);

    float O[16][4];
    #pragma unroll
    for (int n2 = 0; n2 < 16; n2++) { O[n2][0] = O[n2][1] = O[n2][2] = O[n2][3] = 0.f; }
    float lsum_lo = 0.f, lsum_hi = 0.f;

    const int t4   = lane & 3;
    const int src1 = (lane & ~3) | (t4 >> 1);
    const int src2 = src1 + 2;
    const bool odd = t4 & 1;

    for (int kt = 0; kt < NKT; kt++) {
        const int buf = kt & 1;
        if (kt < NKT - 1) {
            const int nb = (kt + 1) & 1;
            const char* ks = kbase + (size_t)(kt + 1) * 4096;
            const char* vs = vbase + (size_t)(kt + 1) * 32768;
            cp16(sb + 8192 + nb * 4096 + tid * 16, ks + tid * 16);
            #pragma unroll
            for (int i = 0; i < 8; i++) { int ch = tid + 256 * i; cp16(sb + 16384 + nb * 32768 + ch * 16, vs + ch * 16); }
            CP_COMMIT();
            CP_WAIT(1);
        } else {
            CP_WAIT(0);
        }
        __syncthreads();

        // ---- QK: S[16 rows][64 keys] per warp (K=16, 2 mma per 8-key block) ----
        float S[8][4];
        #pragma unroll
        for (int nb = 0; nb < 8; nb++) { S[nb][0] = S[nb][1] = S[nb][2] = S[nb][3] = 0.f; }

        #pragma unroll
        for (int nb = 0; nb < 8; nb++) {
            float4 K0 = Ks[buf * 256 + nb * 32 + lane];
            mma8(S[nb], a00, a01, a02, a03, K0.x, K0.y);
            mma8(S[nb], a10, a11, a12, a13, K0.z, K0.w);
        }

        // ---- exp + row sums (quad reduce) ----
        float rlo = 0.f, rhi = 0.f;
        #pragma unroll
        for (int nb = 0; nb < 8; nb++) {
            S[nb][0] = __expf(S[nb][0]);
            S[nb][1] = __expf(S[nb][1]);
            S[nb][2] = __expf(S[nb][2]);
            S[nb][3] = __expf(S[nb][3]);
            rlo += S[nb][0] + S[nb][1];
            rhi += S[nb][2] + S[nb][3];
        }
        rlo += __shfl_xor_sync(0xffffffffu, rlo, 1);
        rlo += __shfl_xor_sync(0xffffffffu, rlo, 2);
        rhi += __shfl_xor_sync(0xffffffffu, rhi, 1);
        rhi += __shfl_xor_sync(0xffffffffu, rhi, 2);
        lsum_lo += rlo;
        lsum_hi += rhi;

        // ---- PV: O[16 rows][128 ch] += P[16][64] * V[64][128] ----
        #pragma unroll
        for (int ksv = 0; ksv < 8; ksv++) {
            float s0 = __shfl_sync(0xffffffffu, S[ksv][0], src1);
            float s1 = __shfl_sync(0xffffffffu, S[ksv][1], src1);
            float s2 = __shfl_sync(0xffffffffu, S[ksv][2], src1);
            float s3 = __shfl_sync(0xffffffffu, S[ksv][3], src1);
            float u0 = __shfl_sync(0xffffffffu, S[ksv][0], src2);
            float u1 = __shfl_sync(0xffffffffu, S[ksv][1], src2);
            float u2 = __shfl_sync(0xffffffffu, S[ksv][2], src2);
            float u3 = __shfl_sync(0xffffffffu, S[ksv][3], src2);
            uint32_t p0 = __float_as_uint(tf32r(odd ? s1 : s0));
            uint32_t p1 = __float_as_uint(tf32r(odd ? s3 : s2));
            uint32_t p2 = __float_as_uint(tf32r(odd ? u1 : u0));
            uint32_t p3 = __float_as_uint(tf32r(odd ? u3 : u2));
            #pragma unroll
            for (int c4 = 0; c4 < 8; c4++) {
                float4 Vf = Vs[buf * 2048 + (ksv * 8 + c4) * 32 + lane];
                mma8(O[2 * c4],     p0, p1, p2, p3, Vf.x, Vf.y);
                mma8(O[2 * c4 + 1], p0, p1, p2, p3, Vf.z, Vf.w);
            }
        }
        __syncthreads();
    }

    // ---- epilogue: normalize + store (out[b][ch][n]) ----
    const float inv_lo = 1.0f / lsum_lo;
    const float inv_hi = 1.0f / lsum_hi;
    const int q_lo = qx * BQ + w * 16 + (lane >> 2);
    const int q_hi = q_lo + 8;
    float* ob = out + (size_t)b * NC * NN;
    #pragma unroll
    for (int n2 = 0; n2 < 16; n2++) {
        int ch = n2 * 8 + 2 * (lane & 3);
        ob[(size_t)ch * NN + q_lo]       = O[n2][0] * inv_lo;
        ob[(size_t)(ch + 1) * NN + q_lo] = O[n2][1] * inv_lo;
        ob[(size_t)ch * NN + q_hi]       = O[n2][2] * inv_hi;
        ob[(size_t)(ch + 1) * NN + q_hi] = O[n2][3] * inv_hi;
    }
}

// ---------------------------------------------------------------------------
extern "C" void kernel_launch(void* const* d_in, const int* in_sizes, int n_in,
                              void* d_out, int out_size)
{
    const float* x  = (const float*)d_in[0];
    const float* Wq = (const float*)d_in[1];
    const float* bq = (const float*)d_in[2];
    const float* Wk = (const float*)d_in[3];
    const float* bk = (const float*)d_in[4];
    const float* Wv = (const float*)d_in[5];
    const float* bv = (const float*)d_in[6];
    float* out = (float*)d_out;

    (void)cudaFuncSetAttribute(proj_kernel, cudaFuncAttributeMaxDynamicSharedMemorySize, PROJ_SMEM);
    (void)cudaFuncSetAttribute(attn_kernel, cudaFuncAttributeMaxDynamicSharedMemorySize, SMEM_TOTAL);

    proj_kernel<<<dim3(NN / 128, NB), 256, PROJ_SMEM>>>(x, Wq, bq, Wk, bk, Wv, bv);
    attn_kernel<<<dim3(NN / BQ, NB), 256, SMEM_TOTAL>>>(out);
}

// round 12
// speedup vs baseline: 14.8975x; 1.6047x over previous
#include <cuda_runtime.h>
#include <cuda_fp16.h>
#include <cstdint>

#define NB 8
#define NC 128
#define NA 16
#define NN 4096
#define BQ 128
#define BKV 64
#define NKT (NN / BKV)   // 64

typedef unsigned long long u64;

// ---------------------------------------------------------------------------
// Portable PTX helpers
// ---------------------------------------------------------------------------
__device__ __forceinline__ uint32_t smem_u32(const void* p) {
    uint32_t a;
    asm("{ .reg .u64 t; cvta.to.shared.u64 t, %1; cvt.u32.u64 %0, t; }" : "=r"(a) : "l"(p));
    return a;
}
__device__ __forceinline__ float tf32r(float x) {   // round-to-nearest tf32
    float y; asm("cvt.rna.tf32.f32 %0,%1;" : "=f"(y) : "f"(x)); return y;
}
__device__ __forceinline__ void cp16(uint32_t dst, const void* src) {
    asm volatile("cp.async.cg.shared.global [%0], [%1], 16;" :: "r"(dst), "l"(src));
}
#define CP_COMMIT() asm volatile("cp.async.commit_group;" ::: "memory")
#define CP_WAIT(n)  asm volatile("cp.async.wait_group %0;" :: "n"(n) : "memory")

__device__ __forceinline__ u64 fma2(u64 a, u64 b, u64 c) {
    u64 d; asm("fma.rn.f32x2 %0,%1,%2,%3;" : "=l"(d) : "l"(a), "l"(b), "l"(c)); return d;
}
__device__ __forceinline__ u64 pack2(float lo, float hi) {
    u64 d; asm("mov.b64 %0,{%1,%2};" : "=l"(d) : "f"(lo), "f"(hi)); return d;
}
__device__ __forceinline__ float2 unpack2(u64 d) {
    float2 r; asm("mov.b64 {%0,%1},%2;" : "=f"(r.x), "=f"(r.y) : "l"(d)); return r;
}
__device__ __forceinline__ uint32_t h2pk(float lo, float hi) {
    __half2 h = __floats2half2_rn(lo, hi);
    return *(uint32_t*)&h;
}

// m16n8k8 tf32 mma: D(f32) += A(tf32) * B(tf32)
__device__ __forceinline__ void mma8(float* d, uint32_t a0, uint32_t a1, uint32_t a2, uint32_t a3,
                                     float bx, float by) {
    asm volatile(
        "mma.sync.aligned.m16n8k8.row.col.f32.tf32.tf32.f32 "
        "{%0,%1,%2,%3}, {%4,%5,%6,%7}, {%8,%9}, {%0,%1,%2,%3};"
        : "+f"(d[0]), "+f"(d[1]), "+f"(d[2]), "+f"(d[3])
        : "r"(a0), "r"(a1), "r"(a2), "r"(a3),
          "r"(__float_as_uint(bx)), "r"(__float_as_uint(by)));
}
// m16n8k16 f16 mma, f32 accumulate
__device__ __forceinline__ void mma16(float* d, uint32_t a0, uint32_t a1, uint32_t a2, uint32_t a3,
                                      uint32_t b0, uint32_t b1) {
    asm volatile(
        "mma.sync.aligned.m16n8k16.row.col.f32.f16.f16.f32 "
        "{%0,%1,%2,%3}, {%4,%5,%6,%7}, {%8,%9}, {%0,%1,%2,%3};"
        : "+f"(d[0]), "+f"(d[1]), "+f"(d[2]), "+f"(d[3])
        : "r"(a0), "r"(a1), "r"(a2), "r"(a3), "r"(b0), "r"(b1));
}

// ---------------------------------------------------------------------------
// Pre-packed operand images (fragment-ordered):
//  g_qp[b][qg=0..255][ks=0..1][lane][4] f32 : Q A-frags (rna tf32, prescaled)
//  g_kp[b][kb=0..511][lane][4] f32          : K B-frags (tf32)
//  g_vph[b][kg16=0..255][c16=0..7][lane][8] f16 :
//      V B-frags for m16n8k16: 16B/lane = {b0,b1}@n8=2c16, {b0,b1}@n8=2c16+1
// ---------------------------------------------------------------------------
__device__ float  g_qp[(size_t)NB * 256 * 2 * 32 * 4];    // 2 MB
__device__ float  g_kp[(size_t)NB * 512 * 32 * 4];        // 2 MB
__device__ __half g_vph[(size_t)NB * 256 * 8 * 32 * 8];   // 8 MB

// ---------------------------------------------------------------------------
// Projection: register-tiled GEMM with packed FFMA2 accumulation.
// Thread (tx,ty) owns 10 o-rows x 8 pixels (4 f32x2 pairs).
// ---------------------------------------------------------------------------
#define WS_STR 17
#define PROJ_SMEM (65536 + 160 * WS_STR * 4)   // 76416 B

__global__ __launch_bounds__(256, 2) void proj_kernel(
    const float* __restrict__ x,
    const float* __restrict__ Wq, const float* __restrict__ bq,
    const float* __restrict__ Wk, const float* __restrict__ bk,
    const float* __restrict__ Wv, const float* __restrict__ bv)
{
    extern __shared__ __align__(16) float ps[];
    float* xs = ps;            // [128 c][128 n]
    float* Ws = ps + 16384;    // [160 o][WS_STR]

    const int b   = blockIdx.y;
    const int n0  = blockIdx.x * 128;
    const int tid = threadIdx.x;
    const int tx  = tid & 15;     // pixel group: n = tx*8..+7
    const int ty  = tid >> 4;     // o group: o = ty*10..+9

    const float* xb = x + ((size_t)b * NC) * NN + n0;
    for (int idx = tid; idx < 128 * 128; idx += 256) {
        int c = idx >> 7, n = idx & 127;
        xs[c * 128 + n] = xb[(size_t)c * NN + n];
    }

    u64 acc2[10][4];
    #pragma unroll
    for (int oo = 0; oo < 10; oo++)
        #pragma unroll
        for (int k = 0; k < 4; k++) acc2[oo][k] = 0ull;

    for (int chunk = 0; chunk < 8; chunk++) {
        __syncthreads();
        for (int idx = tid; idx < 160 * 16; idx += 256) {
            int o = idx >> 4, cc = idx & 15, c = chunk * 16 + cc;
            float wv;
            if (o < 16)      wv = Wq[o * NC + c];
            else if (o < 32) wv = Wk[(o - 16) * NC + c];
            else             wv = Wv[(o - 32) * NC + c];
            Ws[o * WS_STR + cc] = wv;
        }
        __syncthreads();

        #pragma unroll
        for (int cc = 0; cc < 16; cc++) {
            const int c = chunk * 16 + cc;
            float4 xa  = *(const float4*)&xs[c * 128 + tx * 8];
            float4 xb2 = *(const float4*)&xs[c * 128 + tx * 8 + 4];
            u64 xp0 = pack2(xa.x, xa.y),  xp1 = pack2(xa.z, xa.w);
            u64 xp2 = pack2(xb2.x, xb2.y), xp3 = pack2(xb2.z, xb2.w);
            #pragma unroll
            for (int oo = 0; oo < 10; oo++) {
                float wv = Ws[(ty * 10 + oo) * WS_STR + cc];
                u64 wp = pack2(wv, wv);
                acc2[oo][0] = fma2(xp0, wp, acc2[oo][0]);
                acc2[oo][1] = fma2(xp1, wp, acc2[oo][1]);
                acc2[oo][2] = fma2(xp2, wp, acc2[oo][2]);
                acc2[oo][3] = fma2(xp3, wp, acc2[oo][3]);
            }
        }
    }

    // epilogue: bias + round + fragment-pack stores
    #pragma unroll
    for (int oo = 0; oo < 10; oo++) {
        const int o = ty * 10 + oo;
        float acc[8];
        #pragma unroll
        for (int k = 0; k < 4; k++) {
            float2 p = unpack2(acc2[oo][k]);
            acc[2 * k] = p.x; acc[2 * k + 1] = p.y;
        }
        #pragma unroll
        for (int i = 0; i < 8; i++) {
            const int ng = n0 + tx * 8 + i;
            if (o < 16) {
                float q = (acc[i] + bq[o]) * 0.25f;
                float qh = tf32r(q);
                int qg = ng >> 4, g16 = ng & 15;
                int ks = o >> 3, t2 = o & 7;
                int lane = ((g16 & 7) << 2) | (t2 & 3);
                int j = (g16 >> 3) | ((t2 >> 2) << 1);
                g_qp[(((size_t)b * 256 + qg) * 2 + ks) * 128 + lane * 4 + j] = qh;
            } else if (o < 32) {
                int a = o - 16;
                float kh = tf32r(acc[i] + bk[a]);
                int kb = ng >> 3, gk = ng & 7;
                int ks = a >> 3, t2 = a & 7;
                int lane = (gk << 2) | (t2 & 3);
                int j = (ks << 1) | (t2 >> 2);
                g_kp[(((size_t)b * 512 + kb) * 32 + lane) * 4 + j] = kh;
            } else {
                int c = o - 32;
                __half vh = __float2half_rn(acc[i] + bv[c]);
                int r = ng & 15, kg16 = ng >> 4;
                int g = c & 7, t4v = (r & 7) >> 1, j = r >> 3, hsel = r & 1;
                int lane = (g << 2) | t4v;
                int c16 = c >> 4, n8par = (c >> 3) & 1;
                int u16idx = ((n8par << 1) | j) * 2 + hsel;
                g_vph[((((size_t)b * 256 + kg16) * 8 + c16) * 32 + lane) * 8 + u16idx] = vh;
            }
        }
    }
}

// ---------------------------------------------------------------------------
// Flash attention: QK in tf32 mma, PV in fp16 mma (f32 accum), zero shuffles.
// CTA = 128 queries x batch, 8 warps; warp owns 16 rows; no-max softmax.
// dynamic smem: Qs [8KB] @0 | Ks 2x4KB @8192 | Vs(fp16) 2x16KB @16384 = 48KB
// ---------------------------------------------------------------------------
#define SMEM_TOTAL 49152

__global__ __launch_bounds__(256, 2) void attn_kernel(float* __restrict__ out)
{
    extern __shared__ __align__(16) char smc[];
    const float4* Qs = (const float4*)smc;
    const float4* Ks = (const float4*)(smc + 8192);
    const float4* Vs = (const float4*)(smc + 16384);
    const uint32_t sb = smem_u32(smc);

    const int b    = blockIdx.y;
    const int qx   = blockIdx.x;
    const int tid  = threadIdx.x;
    const int w    = tid >> 5;
    const int lane = tid & 31;

    const char* qsrc  = (const char*)g_qp  + ((size_t)b * 256 + qx * 8) * 1024;  // 8KB
    const char* kbase = (const char*)g_kp  + (size_t)b * 512 * 512;              // 4KB per kt
    const char* vbase = (const char*)g_vph + (size_t)b * 256 * 4096;             // 16KB per kt

    // prologue: Q + tile 0
    #pragma unroll
    for (int i = 0; i < 2; i++) { int ch = tid + 256 * i; cp16(sb + ch * 16, qsrc + ch * 16); }
    cp16(sb + 8192 + tid * 16, kbase + tid * 16);
    #pragma unroll
    for (int i = 0; i < 4; i++) { int ch = tid + 256 * i; cp16(sb + 16384 + ch * 16, vbase + ch * 16); }
    CP_COMMIT();
    CP_WAIT(0);
    __syncthreads();

    const float4 A0 = Qs[(w * 2 + 0) * 32 + lane];   // loop-invariant Q A-frags
    const float4 A1 = Qs[(w * 2 + 1) * 32 + lane];
    const uint32_t a00 = __float_as_uint(A0.x), a01 = __float_as_uint(A0.y),
                   a02 = __float_as_uint(A0.z), a03 = __float_as_uint(A0.w);
    const uint32_t a10 = __float_as_uint(A1.x), a11 = __float_as_uint(A1.y),
                   a12 = __float_as_uint(A1.z), a13 = __float_as_uint(A1.w);

    float O[16][4];
    #pragma unroll
    for (int n2 = 0; n2 < 16; n2++) { O[n2][0] = O[n2][1] = O[n2][2] = O[n2][3] = 0.f; }
    float lsum_lo = 0.f, lsum_hi = 0.f;

    for (int kt = 0; kt < NKT; kt++) {
        const int buf = kt & 1;
        if (kt < NKT - 1) {
            const int nb = (kt + 1) & 1;
            cp16(sb + 8192 + nb * 4096 + tid * 16, kbase + (size_t)(kt + 1) * 4096 + tid * 16);
            #pragma unroll
            for (int i = 0; i < 4; i++) {
                int ch = tid + 256 * i;
                cp16(sb + 16384 + nb * 16384 + ch * 16, vbase + (size_t)(kt + 1) * 16384 + ch * 16);
            }
            CP_COMMIT();
            CP_WAIT(1);
        } else {
            CP_WAIT(0);
        }
        __syncthreads();

        // ---- QK (tf32): S[16 rows][64 keys] per warp ----
        float S[8][4];
        #pragma unroll
        for (int nb = 0; nb < 8; nb++) { S[nb][0] = S[nb][1] = S[nb][2] = S[nb][3] = 0.f; }
        #pragma unroll
        for (int nb = 0; nb < 8; nb++) {
            float4 K0 = Ks[buf * 256 + nb * 32 + lane];
            mma8(S[nb], a00, a01, a02, a03, K0.x, K0.y);
            mma8(S[nb], a10, a11, a12, a13, K0.z, K0.w);
        }

        // ---- exp + row sums (quad reduce) ----
        float rlo = 0.f, rhi = 0.f;
        #pragma unroll
        for (int nb = 0; nb < 8; nb++) {
            S[nb][0] = __expf(S[nb][0]);
            S[nb][1] = __expf(S[nb][1]);
            S[nb][2] = __expf(S[nb][2]);
            S[nb][3] = __expf(S[nb][3]);
            rlo += S[nb][0] + S[nb][1];
            rhi += S[nb][2] + S[nb][3];
        }
        rlo += __shfl_xor_sync(0xffffffffu, rlo, 1);
        rlo += __shfl_xor_sync(0xffffffffu, rlo, 2);
        rhi += __shfl_xor_sync(0xffffffffu, rhi, 1);
        rhi += __shfl_xor_sync(0xffffffffu, rhi, 2);
        lsum_lo += rlo;
        lsum_hi += rhi;

        // ---- PV (fp16): O[16 rows][128 ch] += P[16][64] * V[64][128] ----
        // C-frag of QK == A-frag of m16n8k16: pack S pairs as half2, no shuffles.
        #pragma unroll
        for (int ks = 0; ks < 4; ks++) {
            uint32_t pa0 = h2pk(S[2 * ks][0],     S[2 * ks][1]);
            uint32_t pa1 = h2pk(S[2 * ks][2],     S[2 * ks][3]);
            uint32_t pa2 = h2pk(S[2 * ks + 1][0], S[2 * ks + 1][1]);
            uint32_t pa3 = h2pk(S[2 * ks + 1][2], S[2 * ks + 1][3]);
            #pragma unroll
            for (int c16 = 0; c16 < 8; c16++) {
                float4 Vf = Vs[buf * 1024 + (ks * 8 + c16) * 32 + lane];
                mma16(O[2 * c16],     pa0, pa1, pa2, pa3,
                      __float_as_uint(Vf.x), __float_as_uint(Vf.y));
                mma16(O[2 * c16 + 1], pa0, pa1, pa2, pa3,
                      __float_as_uint(Vf.z), __float_as_uint(Vf.w));
            }
        }
        __syncthreads();
    }

    // ---- epilogue: normalize + store (out[b][ch][n]) ----
    const float inv_lo = 1.0f / lsum_lo;
    const float inv_hi = 1.0f / lsum_hi;
    const int q_lo = qx * BQ + w * 16 + (lane >> 2);
    const int q_hi = q_lo + 8;
    float* ob = out + (size_t)b * NC * NN;
    #pragma unroll
    for (int n2 = 0; n2 < 16; n2++) {
        int ch = n2 * 8 + 2 * (lane & 3);
        ob[(size_t)ch * NN + q_lo]       = O[n2][0] * inv_lo;
        ob[(size_t)(ch + 1) * NN + q_lo] = O[n2][1] * inv_lo;
        ob[(size_t)ch * NN + q_hi]       = O[n2][2] * inv_hi;
        ob[(size_t)(ch + 1) * NN + q_hi] = O[n2][3] * inv_hi;
    }
}

// ---------------------------------------------------------------------------
extern "C" void kernel_launch(void* const* d_in, const int* in_sizes, int n_in,
                              void* d_out, int out_size)
{
    const float* x  = (const float*)d_in[0];
    const float* Wq = (const float*)d_in[1];
    const float* bq = (const float*)d_in[2];
    const float* Wk = (const float*)d_in[3];
    const float* bk = (const float*)d_in[4];
    const float* Wv = (const float*)d_in[5];
    const float* bv = (const float*)d_in[6];
    float* out = (float*)d_out;

    (void)cudaFuncSetAttribute(proj_kernel, cudaFuncAttributeMaxDynamicSharedMemorySize, PROJ_SMEM);
    (void)cudaFuncSetAttribute(attn_kernel, cudaFuncAttributeMaxDynamicSharedMemorySize, SMEM_TOTAL);

    proj_kernel<<<dim3(NN / 128, NB), 256, PROJ_SMEM>>>(x, Wq, bq, Wk, bk, Wv, bv);
    attn_kernel<<<dim3(NN / BQ, NB), 256, SMEM_TOTAL>>>(out);
}

// round 14
// speedup vs baseline: 21.3117x; 1.4306x over previous
#include <cuda_runtime.h>
#include <cuda_fp16.h>
#include <cstdint>

#define NB 8
#define NC 128
#define NA 16
#define NN 4096
#define NKT 64    // 64-key tiles

// ---------------------------------------------------------------------------
// Portable PTX helpers
// ---------------------------------------------------------------------------
__device__ __forceinline__ uint32_t smem_u32(const void* p) {
    uint32_t a;
    asm("{ .reg .u64 t; cvta.to.shared.u64 t, %1; cvt.u32.u64 %0, t; }" : "=r"(a) : "l"(p));
    return a;
}
__device__ __forceinline__ float tf32r(float x) {
    float y; asm("cvt.rna.tf32.f32 %0,%1;" : "=f"(y) : "f"(x)); return y;
}
__device__ __forceinline__ void cp16(uint32_t dst, const void* src) {
    asm volatile("cp.async.cg.shared.global [%0], [%1], 16;" :: "r"(dst), "l"(src));
}
#define CP_COMMIT() asm volatile("cp.async.commit_group;" ::: "memory")
#define CP_WAIT(n)  asm volatile("cp.async.wait_group %0;" :: "n"(n) : "memory")

__device__ __forceinline__ uint32_t h2pk(float lo, float hi) {
    __half2 h = __floats2half2_rn(lo, hi);
    return *(uint32_t*)&h;
}

// m16n8k8 tf32 mma
__device__ __forceinline__ void mma8(float* d, uint32_t a0, uint32_t a1, uint32_t a2, uint32_t a3,
                                     float bx, float by) {
    asm volatile(
        "mma.sync.aligned.m16n8k8.row.col.f32.tf32.tf32.f32 "
        "{%0,%1,%2,%3}, {%4,%5,%6,%7}, {%8,%9}, {%0,%1,%2,%3};"
        : "+f"(d[0]), "+f"(d[1]), "+f"(d[2]), "+f"(d[3])
        : "r"(a0), "r"(a1), "r"(a2), "r"(a3),
          "r"(__float_as_uint(bx)), "r"(__float_as_uint(by)));
}
// m16n8k16 f16 mma, f32 accumulate
__device__ __forceinline__ void mma16(float* d, uint32_t a0, uint32_t a1, uint32_t a2, uint32_t a3,
                                      uint32_t b0, uint32_t b1) {
    asm volatile(
        "mma.sync.aligned.m16n8k16.row.col.f32.f16.f16.f32 "
        "{%0,%1,%2,%3}, {%4,%5,%6,%7}, {%8,%9}, {%0,%1,%2,%3};"
        : "+f"(d[0]), "+f"(d[1]), "+f"(d[2]), "+f"(d[3])
        : "r"(a0), "r"(a1), "r"(a2), "r"(a3), "r"(b0), "r"(b1));
}

// ---------------------------------------------------------------------------
// Fragment-packed images (fp16):
//  g_qph[b][qblk=0..255][lane][4 u32]  : Q A-frags m16n8k16 (16 rows x 16 ch)
//  g_kph[b][kb2=0..255][lane][4 u32]   : K B-frags, {b0,b1}@keyblk 2kb2, 2kb2+1
//  g_vph[b][kg16=0..255][c16=0..7][lane][4 u32] : V B-frags (validated R12 layout)
// ---------------------------------------------------------------------------
__device__ __half g_qph[(size_t)NB * 256 * 32 * 8];        // 1 MB
__device__ __half g_kph[(size_t)NB * 256 * 32 * 8];        // 1 MB
__device__ __half g_vph[(size_t)NB * 256 * 8 * 32 * 8];    // 8 MB

// ---------------------------------------------------------------------------
// Projection v3: tensor-core tf32 GEMM, no smem.
// 5 warps x (2 x 16-row blocks): warp0 = {q, k}; warps1-4 = v rows 32(wv-1)+32.
// A = W (tf32, from gmem), B = x (tf32, from gmem, L1-resident tile), C = f32.
// ---------------------------------------------------------------------------
__global__ __launch_bounds__(160, 2) void proj_kernel(
    const float* __restrict__ x,
    const float* __restrict__ Wq, const float* __restrict__ bq,
    const float* __restrict__ Wk, const float* __restrict__ bk,
    const float* __restrict__ Wv, const float* __restrict__ bv)
{
    const int b   = blockIdx.y;
    const int n0  = blockIdx.x * 128;
    const int tid = threadIdx.x;
    const int wv  = tid >> 5, lane = tid & 31;
    const int g   = lane >> 2, t = lane & 3;

    const float *W0, *W1, *B0p, *B1p;
    if (wv == 0) { W0 = Wq; W1 = Wk; B0p = bq; B1p = bk; }
    else {
        W0  = Wv + (size_t)(32 * (wv - 1)) * NC;
        W1  = W0 + 16 * NC;
        B0p = bv + 32 * (wv - 1);
        B1p = B0p + 16;
    }
    const float* xb = x + (size_t)b * NC * NN + n0;

    float acc[2][16][4];
    #pragma unroll
    for (int z = 0; z < 2; z++)
        #pragma unroll
        for (int nb = 0; nb < 16; nb++)
            acc[z][nb][0] = acc[z][nb][1] = acc[z][nb][2] = acc[z][nb][3] = 0.f;

    for (int ks = 0; ks < 16; ks++) {
        const int c0 = ks * 8 + t;
        uint32_t A0[4], A1[4];
        A0[0] = __float_as_uint(tf32r(W0[(size_t)g       * NC + c0]));
        A0[1] = __float_as_uint(tf32r(W0[(size_t)(g + 8) * NC + c0]));
        A0[2] = __float_as_uint(tf32r(W0[(size_t)g       * NC + c0 + 4]));
        A0[3] = __float_as_uint(tf32r(W0[(size_t)(g + 8) * NC + c0 + 4]));
        A1[0] = __float_as_uint(tf32r(W1[(size_t)g       * NC + c0]));
        A1[1] = __float_as_uint(tf32r(W1[(size_t)(g + 8) * NC + c0]));
        A1[2] = __float_as_uint(tf32r(W1[(size_t)g       * NC + c0 + 4]));
        A1[3] = __float_as_uint(tf32r(W1[(size_t)(g + 8) * NC + c0 + 4]));
        #pragma unroll
        for (int nb = 0; nb < 16; nb++) {
            float b0 = tf32r(xb[(size_t)c0       * NN + nb * 8 + g]);
            float b1 = tf32r(xb[(size_t)(c0 + 4) * NN + nb * 8 + g]);
            mma8(acc[0][nb], A0[0], A0[1], A0[2], A0[3], b0, b1);
            mma8(acc[1][nb], A1[0], A1[1], A1[2], A1[3], b0, b1);
        }
    }

    const float bl0 = B0p[g], bh0 = B0p[g + 8];
    const float bl1 = B1p[g], bh1 = B1p[g + 8];

    #pragma unroll
    for (int z = 0; z < 2; z++) {
        const float blo = z ? bl1 : bl0;
        const float bhi = z ? bh1 : bh0;
        #pragma unroll
        for (int nb = 0; nb < 16; nb++) {
            float v0 = acc[z][nb][0] + blo;
            float v1 = acc[z][nb][1] + blo;
            float v2 = acc[z][nb][2] + bhi;
            float v3 = acc[z][nb][3] + bhi;
            const int px0 = n0 + nb * 8 + 2 * t;
            if (wv == 0) {
                if (z == 0) { v0 *= 0.25f; v1 *= 0.25f; v2 *= 0.25f; v3 *= 0.25f; }
                const float vals[4] = {v0, v1, v2, v3};
                #pragma unroll
                for (int e = 0; e < 4; e++) {
                    const int a  = (e >> 1) ? g + 8 : g;
                    const int px = px0 + (e & 1);
                    const int r  = px & 15;
                    if (z == 0) {   // q -> A-frag layout
                        int qblk = px >> 4;
                        int lp = ((r & 7) << 2) | ((a & 7) >> 1);
                        int j  = (r >> 3) | ((a >> 3) << 1);
                        g_qph[(((size_t)b * 256 + qblk) * 32 + lp) * 8 + j * 2 + (a & 1)] =
                            __float2half_rn(vals[e]);
                    } else {        // k -> B-frag layout
                        int kb2 = px >> 4;
                        int pj = (r >> 3) & 1, kk = r & 7;
                        int lp = (kk << 2) | ((a & 7) >> 1);
                        int ui = (pj << 1) | (a >> 3);
                        g_kph[(((size_t)b * 256 + kb2) * 32 + lp) * 8 + ui * 2 + (a & 1)] =
                            __float2half_rn(vals[e]);
                    }
                }
            } else {   // v -> B-frag image (R12-validated layout); pair stores
                const int kg16 = px0 >> 4, r = px0 & 15;
                const int t4v = (r & 7) >> 1, j = r >> 3;
                const int c_lo = 32 * (wv - 1) + 16 * z + g;
                #pragma unroll
                for (int e = 0; e < 2; e++) {
                    const int c = c_lo + 8 * e;
                    int lp = ((c & 7) << 2) | t4v;
                    int c16 = c >> 4, n8par = (c >> 3) & 1;
                    int u = (n8par << 1) | j;
                    ((uint32_t*)g_vph)[((((size_t)b * 256 + kg16) * 8 + c16) * 32 + lp) * 4 + u] =
                        e ? h2pk(v2, v3) : h2pk(v0, v1);
                }
            }
        }
    }
}

// ---------------------------------------------------------------------------
// Flash attention v3: all-fp16 mma (f32 accum), 4 warps x 32 rows, 128 thr.
// Each V fragment feeds 4 mma (2 row-blocks x 2 ch-blocks).
// smem: Qs 4KB @0 | Ks 2x2KB @4096 | Vs 2x16KB @8192  -> 40KB
// ---------------------------------------------------------------------------
#define SMEM_TOTAL 40960

__global__ __launch_bounds__(128, 2) void attn_kernel(float* __restrict__ out)
{
    extern __shared__ __align__(16) char smc[];
    const uint4* Qs = (const uint4*)smc;
    const uint4* Ks = (const uint4*)(smc + 4096);
    const uint4* Vs = (const uint4*)(smc + 8192);
    const uint32_t sb = smem_u32(smc);

    const int b    = blockIdx.y;
    const int qx   = blockIdx.x;
    const int tid  = threadIdx.x;
    const int w    = tid >> 5;
    const int lane = tid & 31;

    const char* qsrc  = (const char*)g_qph + ((size_t)b * 256 + qx * 8) * 512;  // 4KB
    const char* kbase = (const char*)g_kph + (size_t)b * 256 * 512;             // 2KB per kt
    const char* vbase = (const char*)g_vph + (size_t)b * 256 * 4096;            // 16KB per kt

    // prologue: Q + tile 0
    #pragma unroll
    for (int i = 0; i < 2; i++) { int c = (tid + 128 * i) * 16; cp16(sb + c, qsrc + c); }
    cp16(sb + 4096 + tid * 16, kbase + tid * 16);
    #pragma unroll
    for (int i = 0; i < 8; i++) { int c = (tid + 128 * i) * 16; cp16(sb + 8192 + c, vbase + c); }
    CP_COMMIT();
    CP_WAIT(0);
    __syncthreads();

    const uint4 af[2] = { Qs[(2 * w + 0) * 32 + lane], Qs[(2 * w + 1) * 32 + lane] };

    float O[2][16][4];
    #pragma unroll
    for (int z = 0; z < 2; z++)
        #pragma unroll
        for (int n2 = 0; n2 < 16; n2++)
            O[z][n2][0] = O[z][n2][1] = O[z][n2][2] = O[z][n2][3] = 0.f;
    float ls[2][2] = {{0.f, 0.f}, {0.f, 0.f}};

    for (int kt = 0; kt < NKT; kt++) {
        const int buf = kt & 1;
        if (kt < NKT - 1) {
            const int nb = (kt + 1) & 1;
            cp16(sb + 4096 + nb * 2048 + tid * 16, kbase + (size_t)(kt + 1) * 2048 + tid * 16);
            #pragma unroll
            for (int i = 0; i < 8; i++) {
                int c = (tid + 128 * i) * 16;
                cp16(sb + 8192 + nb * 16384 + c, vbase + (size_t)(kt + 1) * 16384 + c);
            }
            CP_COMMIT();
            CP_WAIT(1);
        } else {
            CP_WAIT(0);
        }
        __syncthreads();

        uint32_t P[2][4][4];
        #pragma unroll
        for (int z = 0; z < 2; z++) {
            // QK (fp16 m16n8k16): S[16 rows][64 keys]
            float S[8][4];
            #pragma unroll
            for (int nb = 0; nb < 8; nb++) S[nb][0] = S[nb][1] = S[nb][2] = S[nb][3] = 0.f;
            #pragma unroll
            for (int j2 = 0; j2 < 4; j2++) {
                uint4 Kf = Ks[buf * 128 + j2 * 32 + lane];
                mma16(S[2 * j2],     af[z].x, af[z].y, af[z].z, af[z].w, Kf.x, Kf.y);
                mma16(S[2 * j2 + 1], af[z].x, af[z].y, af[z].z, af[z].w, Kf.z, Kf.w);
            }
            // exp + row sums
            float rlo = 0.f, rhi = 0.f;
            #pragma unroll
            for (int nb = 0; nb < 8; nb++) {
                S[nb][0] = __expf(S[nb][0]);
                S[nb][1] = __expf(S[nb][1]);
                S[nb][2] = __expf(S[nb][2]);
                S[nb][3] = __expf(S[nb][3]);
                rlo += S[nb][0] + S[nb][1];
                rhi += S[nb][2] + S[nb][3];
            }
            rlo += __shfl_xor_sync(0xffffffffu, rlo, 1);
            rlo += __shfl_xor_sync(0xffffffffu, rlo, 2);
            rhi += __shfl_xor_sync(0xffffffffu, rhi, 1);
            rhi += __shfl_xor_sync(0xffffffffu, rhi, 2);
            ls[z][0] += rlo;
            ls[z][1] += rhi;
            // pack P (C-frag == A-frag layout)
            #pragma unroll
            for (int ks = 0; ks < 4; ks++) {
                P[z][ks][0] = h2pk(S[2 * ks][0],     S[2 * ks][1]);
                P[z][ks][1] = h2pk(S[2 * ks][2],     S[2 * ks][3]);
                P[z][ks][2] = h2pk(S[2 * ks + 1][0], S[2 * ks + 1][1]);
                P[z][ks][3] = h2pk(S[2 * ks + 1][2], S[2 * ks + 1][3]);
            }
        }

        // PV: each V fragment feeds both row-blocks (4 mma per LDS.128)
        #pragma unroll
        for (int ks = 0; ks < 4; ks++) {
            #pragma unroll
            for (int c16 = 0; c16 < 8; c16++) {
                uint4 Vf = Vs[buf * 1024 + (ks * 8 + c16) * 32 + lane];
                mma16(O[0][2 * c16],     P[0][ks][0], P[0][ks][1], P[0][ks][2], P[0][ks][3], Vf.x, Vf.y);
                mma16(O[0][2 * c16 + 1], P[0][ks][0], P[0][ks][1], P[0][ks][2], P[0][ks][3], Vf.z, Vf.w);
                mma16(O[1][2 * c16],     P[1][ks][0], P[1][ks][1], P[1][ks][2], P[1][ks][3], Vf.x, Vf.y);
                mma16(O[1][2 * c16 + 1], P[1][ks][0], P[1][ks][1], P[1][ks][2], P[1][ks][3], Vf.z, Vf.w);
            }
        }
        __syncthreads();
    }

    // epilogue: normalize + store out[b][ch][n]
    float* ob = out + (size_t)b * NC * NN;
    #pragma unroll
    for (int z = 0; z < 2; z++) {
        const float inv_lo = 1.0f / ls[z][0];
        const float inv_hi = 1.0f / ls[z][1];
        const int base = qx * 128 + (2 * w + z) * 16;
        const int q_lo = base + (lane >> 2);
        const int q_hi = q_lo + 8;
        #pragma unroll
        for (int n2 = 0; n2 < 16; n2++) {
            int ch = n2 * 8 + 2 * (lane & 3);
            ob[(size_t)ch * NN + q_lo]       = O[z][n2][0] * inv_lo;
            ob[(size_t)(ch + 1) * NN + q_lo] = O[z][n2][1] * inv_lo;
            ob[(size_t)ch * NN + q_hi]       = O[z][n2][2] * inv_hi;
            ob[(size_t)(ch + 1) * NN + q_hi] = O[z][n2][3] * inv_hi;
        }
    }
}

// ---------------------------------------------------------------------------
extern "C" void kernel_launch(void* const* d_in, const int* in_sizes, int n_in,
                              void* d_out, int out_size)
{
    const float* x  = (const float*)d_in[0];
    const float* Wq = (const float*)d_in[1];
    const float* bq = (const float*)d_in[2];
    const float* Wk = (const float*)d_in[3];
    const float* bk = (const float*)d_in[4];
    const float* Wv = (const float*)d_in[5];
    const float* bv = (const float*)d_in[6];
    float* out = (float*)d_out;

    (void)cudaFuncSetAttribute(attn_kernel, cudaFuncAttributeMaxDynamicSharedMemorySize, SMEM_TOTAL);

    proj_kernel<<<dim3(NN / 128, NB), 160>>>(x, Wq, bq, Wk, bk, Wv, bv);
    attn_kernel<<<dim3(NN / 128, NB), 128, SMEM_TOTAL>>>(out);
}